// round 4
// baseline (speedup 1.0000x reference)
#include <cuda_runtime.h>
#include <math.h>

// ---------------------------------------------------------------------------
// ContrastiveEnergyLearning — Round 3: software-pipelined FFMA2 GEMMs.
// Double-buffered register prefetch of x-tiles and pair-packed weights removes
// LDS->FMA scoreboard stalls; arithmetic identical to round 2.
// ---------------------------------------------------------------------------

#define NB      32768
#define RPB     17
#define RTOT    (NB * RPB)          // 557056
#define TILE_M  64
#define NBLK    (RTOT / TILE_M)     // 8704
#define TEMP_INV (1.0f / 0.07f)

__device__ float g_A[NB * 256];     // anchor @ W1x^T + b1
__device__ float g_energy[RTOT];
__device__ float g_part[128][4];

typedef unsigned long long u64;

__device__ __forceinline__ u64 pk(float x, float y) {
    u64 r; asm("mov.b64 %0,{%1,%2};" : "=l"(r) : "f"(x), "f"(y)); return r;
}
__device__ __forceinline__ float2 upk(u64 v) {
    float2 r; asm("mov.b64 {%0,%1},%2;" : "=f"(r.x), "=f"(r.y) : "l"(v)); return r;
}
__device__ __forceinline__ void fma2(u64 &d, u64 a, u64 b) {
    asm("fma.rn.f32x2 %0,%1,%2,%0;" : "+l"(d) : "l"(a), "l"(b));
}
__device__ __forceinline__ float gelu_exact(float x) {
    return 0.5f * x * (1.0f + erff(x * 0.7071067811865476f));
}
__device__ __forceinline__ float f4el(const float4& v, int c) {
    return (c == 0) ? v.x : (c == 1) ? v.y : (c == 2) ? v.z : v.w;
}

// ---------------------------------------------------------------------------
// Weight staging into pair-packed SMEM (same layout as round 2):
// pair j of lane l at local k holds (W[l+64j][k], W[l+64j+32][k]).
//   NO>=128: ulonglong2 slot (k*(NO/128)+jj)*32 + l  (16B lane stride)
//   NO==64 : u64 slot k*32 + l                        (8B lane stride)
// ---------------------------------------------------------------------------
template <int NO, int KC>
__device__ __forceinline__ void load_wp(float* Wp, const float* __restrict__ W,
                                        int ld, int k0, int tid) {
    constexpr int NQ = KC / 4;
    #pragma unroll
    for (int i = tid; i < NO * NQ; i += 256) {
        int o  = i / NQ;
        int kg = i - o * NQ;
        float4 v = *(const float4*)(W + (size_t)o * ld + k0 + (kg << 2));
        int l = o & 31, h = o >> 5;
        int j = h >> 1, half = h & 1;
        float vv[4] = {v.x, v.y, v.z, v.w};
        #pragma unroll
        for (int c = 0; c < 4; c++) {
            int k = (kg << 2) + c;
            int fidx;
            if (NO >= 128) {
                int jj = j >> 1, jb = j & 1;
                fidx = ((((k * (NO / 128) + jj) * 32 + l) * 2 + jb) * 2) + half;
            } else {
                fidx = (k * 32 + l) * 2 + half;
            }
            Wp[fidx] = vv[c];
        }
    }
}

// ---------------------------------------------------------------------------
// Pipelined 64x256 GEMM chunk (KC=64). acc[i][j] = outputs (l+64j, l+64j+32).
// Register double-buffering: prefetch (xv, w) for k4+4 before computing k4.
// ---------------------------------------------------------------------------
struct W256 { ulonglong2 a[4]; ulonglong2 b[4]; };

__device__ __forceinline__ void ldx8(float4 x[8], const float* Xs, int m0, int off) {
    #pragma unroll
    for (int i = 0; i < 8; i++)
        x[i] = *(const float4*)&Xs[(m0 + i) * 256 + off];
}
__device__ __forceinline__ void ldw256(W256& w, const ulonglong2* Wv, int k4, int l) {
    #pragma unroll
    for (int c = 0; c < 4; c++) {
        w.a[c] = Wv[((k4 + c) * 2 + 0) * 32 + l];
        w.b[c] = Wv[((k4 + c) * 2 + 1) * 32 + l];
    }
}
__device__ __forceinline__ void fma256(const float4 x[8], const W256& w, u64 acc[8][4]) {
    #pragma unroll
    for (int c = 0; c < 4; c++) {
        #pragma unroll
        for (int i = 0; i < 8; i++) {
            u64 xx = pk(f4el(x[i], c), f4el(x[i], c));
            fma2(acc[i][0], xx, w.a[c].x);
            fma2(acc[i][1], xx, w.a[c].y);
            fma2(acc[i][2], xx, w.b[c].x);
            fma2(acc[i][3], xx, w.b[c].y);
        }
    }
}

__device__ __forceinline__ void gemm256_pipe(const float* Xs, const float* Wst,
                                             int kc, int m0, int l, u64 acc[8][4]) {
    const ulonglong2* Wv = (const ulonglong2*)Wst;
    float4 xa[8], xb[8];
    W256 wa, wb;
    ldx8(xa, Xs, m0, kc);
    ldw256(wa, Wv, 0, l);
    #pragma unroll
    for (int k4 = 0; k4 < 64; k4 += 8) {
        ldx8(xb, Xs, m0, kc + k4 + 4);
        ldw256(wb, Wv, k4 + 4, l);
        fma256(xa, wa, acc);
        if (k4 + 8 < 64) {
            ldx8(xa, Xs, m0, kc + k4 + 8);
            ldw256(wa, Wv, k4 + 8, l);
        }
        fma256(xb, wb, acc);
    }
}

// ---------------------------------------------------------------------------
// Kernel 1: g_A = anchor @ W1[:, :256]^T + b1
// ---------------------------------------------------------------------------
__global__ void __launch_bounds__(256, 1)
precompA(const float* __restrict__ anchor, const float* __restrict__ W1,
         const float* __restrict__ b1) {
    extern __shared__ float sm[];
    float* Xs  = sm;             // 64*256
    float* Wst = sm + 16384;     // 16384 floats

    const int tid = threadIdx.x;
    const int r0  = blockIdx.x * TILE_M;

    for (int i = tid; i < 64 * 64; i += 256) {
        int m = i >> 6, c = i & 63;
        ((float4*)Xs)[m * 64 + c] =
            ((const float4*)(anchor + (size_t)(r0 + m) * 256))[c];
    }

    const int m0 = (tid >> 5) * 8;
    const int l  = tid & 31;

    u64 bv[4];
    #pragma unroll
    for (int j = 0; j < 4; j++) bv[j] = pk(b1[l + 64 * j], b1[l + 64 * j + 32]);
    u64 acc[8][4];
    #pragma unroll
    for (int i = 0; i < 8; i++)
        #pragma unroll
        for (int j = 0; j < 4; j++) acc[i][j] = bv[j];

    for (int kc = 0; kc < 256; kc += 64) {
        __syncthreads();
        load_wp<256, 64>(Wst, W1, 512, kc, tid);
        __syncthreads();
        gemm256_pipe(Xs, Wst, kc, m0, l, acc);
    }

    #pragma unroll
    for (int i = 0; i < 8; i++) {
        size_t base = (size_t)(r0 + m0 + i) * 256 + l;
        #pragma unroll
        for (int j = 0; j < 4; j++) {
            float2 p = upk(acc[i][j]);
            g_A[base + 64 * j]      = p.x;
            g_A[base + 64 * j + 32] = p.y;
        }
    }
}

// ---------------------------------------------------------------------------
// Kernel 2: fused energy
// ---------------------------------------------------------------------------
__global__ void __launch_bounds__(256, 1)
energyK(const float* __restrict__ positive, const float* __restrict__ negatives,
        const float* __restrict__ W1, const float* __restrict__ W2,
        const float* __restrict__ b2, const float* __restrict__ W3,
        const float* __restrict__ b3, const float* __restrict__ W4,
        const float* __restrict__ b4) {
    extern __shared__ float sm[];
    float* Ys  = sm;              // 16384 floats
    float* H1s = sm + 16384;      // 16384
    float* Wst = sm + 32768;      // 16384
    float* H2s = sm;              // 64*128 (reuses Ys)
    float* H3s = sm + 8192;       // 64*65 padded (inside old Ys)

    const int tid = threadIdx.x;
    const int r0  = blockIdx.x * TILE_M;

    // assemble Y tile
    for (int i = tid; i < 64 * 64; i += 256) {
        int m = i >> 6, c = i & 63;
        int r = r0 + m;
        int b = r / 17;
        int j = r - b * 17;
        const float* src = (j == 0) ? positive + (size_t)b * 256
                                    : negatives + ((size_t)b * 16 + (j - 1)) * 256;
        ((float4*)Ys)[m * 64 + c] = ((const float4*)src)[c];
    }

    const int m0 = (tid >> 5) * 8;
    const int l  = tid & 31;

    // init accumulators from precomputed anchor partial (contains b1)
    u64 acc[8][4];
    #pragma unroll
    for (int i = 0; i < 8; i++) {
        int r = r0 + m0 + i;
        int b = r / 17;
        const float* a = g_A + (size_t)b * 256 + l;
        #pragma unroll
        for (int j = 0; j < 4; j++)
            acc[i][j] = pk(a[64 * j], a[64 * j + 32]);
    }

    // ---- layer 1 (y half): K=256 over W1[:, 256:512]
    for (int kc = 0; kc < 256; kc += 64) {
        __syncthreads();
        load_wp<256, 64>(Wst, W1 + 256, 512, kc, tid);
        __syncthreads();
        gemm256_pipe(Ys, Wst, kc, m0, l, acc);
    }

    // gelu -> H1s
    #pragma unroll
    for (int i = 0; i < 8; i++) {
        float* hr = &H1s[(m0 + i) * 256 + l];
        #pragma unroll
        for (int j = 0; j < 4; j++) {
            float2 p = upk(acc[i][j]);
            hr[64 * j]      = gelu_exact(p.x);
            hr[64 * j + 32] = gelu_exact(p.y);
        }
    }

    // ---- layer 2: 64x128, K=256 (pipelined)
    u64 acc2[8][2];
    #pragma unroll
    for (int i = 0; i < 8; i++) { acc2[i][0] = 0ULL; acc2[i][1] = 0ULL; }

    for (int kc = 0; kc < 256; kc += 64) {
        __syncthreads();
        load_wp<128, 64>(Wst, W2, 256, kc, tid);
        __syncthreads();
        const ulonglong2* Wv = (const ulonglong2*)Wst;
        float4 xa[8], xb[8];
        ulonglong2 wa[4], wb[4];
        #pragma unroll
        for (int i = 0; i < 8; i++) xa[i] = *(const float4*)&H1s[(m0 + i) * 256 + kc];
        #pragma unroll
        for (int c = 0; c < 4; c++) wa[c] = Wv[c * 32 + l];
        #pragma unroll
        for (int k4 = 0; k4 < 64; k4 += 8) {
            #pragma unroll
            for (int i = 0; i < 8; i++) xb[i] = *(const float4*)&H1s[(m0 + i) * 256 + kc + k4 + 4];
            #pragma unroll
            for (int c = 0; c < 4; c++) wb[c] = Wv[(k4 + 4 + c) * 32 + l];
            #pragma unroll
            for (int c = 0; c < 4; c++)
                #pragma unroll
                for (int i = 0; i < 8; i++) {
                    u64 xx = pk(f4el(xa[i], c), f4el(xa[i], c));
                    fma2(acc2[i][0], xx, wa[c].x);
                    fma2(acc2[i][1], xx, wa[c].y);
                }
            if (k4 + 8 < 64) {
                #pragma unroll
                for (int i = 0; i < 8; i++) xa[i] = *(const float4*)&H1s[(m0 + i) * 256 + kc + k4 + 8];
                #pragma unroll
                for (int c = 0; c < 4; c++) wa[c] = Wv[(k4 + 8 + c) * 32 + l];
            }
            #pragma unroll
            for (int c = 0; c < 4; c++)
                #pragma unroll
                for (int i = 0; i < 8; i++) {
                    u64 xx = pk(f4el(xb[i], c), f4el(xb[i], c));
                    fma2(acc2[i][0], xx, wb[c].x);
                    fma2(acc2[i][1], xx, wb[c].y);
                }
        }
    }

    __syncthreads();  // all Wst/Ys reads done before H2s store + W3 staging
    {
        float b2a = b2[l], b2b = b2[l + 32], b2c = b2[l + 64], b2d = b2[l + 96];
        #pragma unroll
        for (int i = 0; i < 8; i++) {
            float2 p0 = upk(acc2[i][0]), p1 = upk(acc2[i][1]);
            float* hr = &H2s[(m0 + i) * 128 + l];
            hr[0]  = gelu_exact(p0.x + b2a);
            hr[32] = gelu_exact(p0.y + b2b);
            hr[64] = gelu_exact(p1.x + b2c);
            hr[96] = gelu_exact(p1.y + b2d);
        }
    }
    load_wp<64, 128>(Wst, W3, 128, 0, tid);
    __syncthreads();

    // ---- layer 3: 64x64, K=128 (pipelined)
    u64 acc3[8];
    #pragma unroll
    for (int i = 0; i < 8; i++) acc3[i] = 0ULL;

    {
        const u64* Wv3 = (const u64*)Wst;
        float4 xa[8], xb[8];
        u64 wa[4], wb[4];
        #pragma unroll
        for (int i = 0; i < 8; i++) xa[i] = *(const float4*)&H2s[(m0 + i) * 128];
        #pragma unroll
        for (int c = 0; c < 4; c++) wa[c] = Wv3[c * 32 + l];
        #pragma unroll
        for (int k4 = 0; k4 < 128; k4 += 8) {
            #pragma unroll
            for (int i = 0; i < 8; i++) xb[i] = *(const float4*)&H2s[(m0 + i) * 128 + k4 + 4];
            #pragma unroll
            for (int c = 0; c < 4; c++) wb[c] = Wv3[(k4 + 4 + c) * 32 + l];
            #pragma unroll
            for (int c = 0; c < 4; c++)
                #pragma unroll
                for (int i = 0; i < 8; i++) {
                    u64 xx = pk(f4el(xa[i], c), f4el(xa[i], c));
                    fma2(acc3[i], xx, wa[c]);
                }
            if (k4 + 8 < 128) {
                #pragma unroll
                for (int i = 0; i < 8; i++) xa[i] = *(const float4*)&H2s[(m0 + i) * 128 + k4 + 8];
                #pragma unroll
                for (int c = 0; c < 4; c++) wa[c] = Wv3[(k4 + 8 + c) * 32 + l];
            }
            #pragma unroll
            for (int c = 0; c < 4; c++)
                #pragma unroll
                for (int i = 0; i < 8; i++) {
                    u64 xx = pk(f4el(xb[i], c), f4el(xb[i], c));
                    fma2(acc3[i], xx, wb[c]);
                }
        }
    }

    {
        float b3a = b3[l], b3b = b3[l + 32];
        #pragma unroll
        for (int i = 0; i < 8; i++) {
            float2 p = upk(acc3[i]);
            H3s[(m0 + i) * 65 + l]      = gelu_exact(p.x + b3a);
            H3s[(m0 + i) * 65 + l + 32] = gelu_exact(p.y + b3b);
        }
    }

    __syncthreads();              // H3s complete, layer-3 Wst reads done
    if (tid < 64) Wst[tid] = W4[tid];
    __syncthreads();

    // ---- layer 4: dot(64) + b4
    if (tid < 64) {
        float e = b4[0];
        const float* hr = &H3s[tid * 65];
        #pragma unroll
        for (int k = 0; k < 64; k++) e += hr[k] * Wst[k];
        g_energy[r0 + tid] = e;
    }
}

// ---------------------------------------------------------------------------
// Reductions (deterministic trees, no atomics)
// ---------------------------------------------------------------------------
__global__ void reduce1() {
    __shared__ float sl[256], sp[256], sn[256], sa[256];
    const int t = threadIdx.x;
    const int b = blockIdx.x * 256 + t;
    const float* e = &g_energy[(size_t)b * 17];

    float v[17];
    #pragma unroll
    for (int j = 0; j < 17; j++) v[j] = e[j];

    float l0 = -v[0] * TEMP_INV;
    float mx = l0;
    #pragma unroll
    for (int j = 1; j < 17; j++) mx = fmaxf(mx, -v[j] * TEMP_INV);
    float s = 0.f;
    #pragma unroll
    for (int j = 0; j < 17; j++) s += expf(-v[j] * TEMP_INV - mx);
    float loss = mx + logf(s) - l0;

    float pos = v[0];
    float neg = 0.f;
    float ok  = 1.f;
    #pragma unroll
    for (int j = 1; j < 17; j++) {
        neg += v[j];
        if (v[j] < v[0]) ok = 0.f;
    }

    sl[t] = loss; sp[t] = pos; sn[t] = neg; sa[t] = ok;
    __syncthreads();
    for (int st = 128; st > 0; st >>= 1) {
        if (t < st) {
            sl[t] += sl[t + st]; sp[t] += sp[t + st];
            sn[t] += sn[t + st]; sa[t] += sa[t + st];
        }
        __syncthreads();
    }
    if (t == 0) {
        g_part[blockIdx.x][0] = sl[0];
        g_part[blockIdx.x][1] = sp[0];
        g_part[blockIdx.x][2] = sn[0];
        g_part[blockIdx.x][3] = sa[0];
    }
}

__global__ void reduce2(float* __restrict__ out) {
    __shared__ float s[128][4];
    const int t = threadIdx.x;
    #pragma unroll
    for (int c = 0; c < 4; c++) s[t][c] = g_part[t][c];
    __syncthreads();
    for (int st = 64; st > 0; st >>= 1) {
        if (t < st) {
            #pragma unroll
            for (int c = 0; c < 4; c++) s[t][c] += s[t + st][c];
        }
        __syncthreads();
    }
    if (t == 0) {
        out[0] = s[0][0] / 32768.0f;
        out[1] = s[0][1] / 32768.0f;
        out[2] = s[0][2] / (32768.0f * 16.0f);
        out[3] = s[0][3] / 32768.0f;
    }
}

// ---------------------------------------------------------------------------
extern "C" void kernel_launch(void* const* d_in, const int* in_sizes, int n_in,
                              void* d_out, int out_size) {
    const float* anchor    = (const float*)d_in[0];
    const float* positive  = (const float*)d_in[1];
    const float* negatives = (const float*)d_in[2];
    const float* W1 = (const float*)d_in[3];
    const float* b1 = (const float*)d_in[4];
    const float* W2 = (const float*)d_in[5];
    const float* b2 = (const float*)d_in[6];
    const float* W3 = (const float*)d_in[7];
    const float* b3 = (const float*)d_in[8];
    const float* W4 = (const float*)d_in[9];
    const float* b4 = (const float*)d_in[10];
    float* out = (float*)d_out;

    const int SMEM_PRE = (16384 + 16384) * 4;          // 128 KB
    const int SMEM_EN  = (16384 * 3) * 4;              // 192 KB
    cudaFuncSetAttribute(precompA, cudaFuncAttributeMaxDynamicSharedMemorySize, SMEM_PRE);
    cudaFuncSetAttribute(energyK,  cudaFuncAttributeMaxDynamicSharedMemorySize, SMEM_EN);

    precompA<<<NB / TILE_M, 256, SMEM_PRE>>>(anchor, W1, b1);
    energyK<<<NBLK, 256, SMEM_EN>>>(positive, negatives, W1, W2, b2, W3, b3, W4, b4);
    reduce1<<<128, 256>>>();
    reduce2<<<1, 128>>>(out);
}